// round 1
// baseline (speedup 1.0000x reference)
#include <cuda_runtime.h>
#include <math.h>

#define BB 4
#define SS 2048
#define DM 1024
#define NH 16
#define DK 64
#define MTOT (BB*SS)

// scratch (device globals; allocation-free at launch time)
__device__ float g_Q[(size_t)MTOT*DM];
__device__ float g_K[(size_t)MTOT*DM];
__device__ float g_V[(size_t)MTOT*DM];
__device__ float g_C[(size_t)MTOT*DM];

// ---------------------------------------------------------------------------
// Tiled SGEMM: C[M,N] = A[M,K] * W[K,N], all row-major. BM=BN=64, BK=16,
// 256 threads, 4x4 register tile per thread.
// ---------------------------------------------------------------------------
__global__ void sgemm64(const float* __restrict__ A, const float* __restrict__ W,
                        float* __restrict__ C, int Mdim, int Ndim, int Kdim) {
    __shared__ float As[16][64];   // [k][m]
    __shared__ float Bs[16][64];   // [k][n]

    const int tid = threadIdx.x;
    const int tx = tid & 15;
    const int ty = tid >> 4;
    const int m0 = blockIdx.y * 64;
    const int n0 = blockIdx.x * 64;

    float acc[4][4] = {};

    for (int k0 = 0; k0 < Kdim; k0 += 16) {
        // load A tile (64 rows x 16 k) transposed into As[k][m]
        {
            const int r  = tid >> 2;          // 0..63
            const int kc = (tid & 3) * 4;     // 0,4,8,12
            float4 a = *(const float4*)&A[(size_t)(m0 + r) * Kdim + k0 + kc];
            As[kc + 0][r] = a.x;
            As[kc + 1][r] = a.y;
            As[kc + 2][r] = a.z;
            As[kc + 3][r] = a.w;
        }
        // load B tile (16 k x 64 n) direct
        {
            const int kr = tid >> 4;          // 0..15
            const int nc = (tid & 15) * 4;    // 0..60
            *(float4*)&Bs[kr][nc] =
                *(const float4*)&W[(size_t)(k0 + kr) * Ndim + n0 + nc];
        }
        __syncthreads();

        #pragma unroll
        for (int k = 0; k < 16; k++) {
            float4 a = *(float4*)&As[k][ty * 4];
            float4 b = *(float4*)&Bs[k][tx * 4];
            float av[4] = {a.x, a.y, a.z, a.w};
            float bv[4] = {b.x, b.y, b.z, b.w};
            #pragma unroll
            for (int i = 0; i < 4; i++)
                #pragma unroll
                for (int j = 0; j < 4; j++)
                    acc[i][j] = fmaf(av[i], bv[j], acc[i][j]);
        }
        __syncthreads();
    }

    #pragma unroll
    for (int i = 0; i < 4; i++) {
        float4 o = make_float4(acc[i][0], acc[i][1], acc[i][2], acc[i][3]);
        *(float4*)&C[(size_t)(m0 + ty * 4 + i) * Ndim + n0 + tx * 4] = o;
    }
}

// ---------------------------------------------------------------------------
// RoPE (interleaved-pair convention from reference): operates in place.
// One thread per (row, pair). pos = row % S, i = pair index within head (0..31).
// ---------------------------------------------------------------------------
__global__ void rope_kernel(float* __restrict__ X, int total_pairs) {
    int idx = blockIdx.x * blockDim.x + threadIdx.x;
    if (idx >= total_pairs) return;
    const int p   = idx & 511;          // pair within row (0..511)
    const int m   = idx >> 9;           // row
    const int pos = m & (SS - 1);
    const int i   = p & 31;             // pair within head

    // inv_freq = 10000^(-i/32); compute in double for accuracy
    double inv = exp(-(double)i / 32.0 * log(10000.0));
    float ang = (float)((double)pos * inv);
    float c, s;
    __sincosf(ang, &s, &c);             // fast path; overwritten below for accuracy
    sincosf(ang, &s, &c);

    float* base = X + (size_t)m * DM + p * 2;
    float x1 = base[0];
    float x2 = base[1];
    base[0] = x1 * c - x2 * s;
    base[1] = x1 * s + x2 * c;
}

// ---------------------------------------------------------------------------
// Flash attention, fp32. One CTA per (q-tile of 64, head, batch).
// 256 threads; BM=BN=DK=64; online softmax; O accumulators in registers.
// ---------------------------------------------------------------------------
__global__ void flash_attn(const float* __restrict__ Q, const float* __restrict__ K,
                           const float* __restrict__ V, float* __restrict__ O) {
    extern __shared__ float sm[];
    float* Qs    = sm;                 // [d][q]   64x64
    float* Ks    = Qs + 64 * 64;       // [d][k]   64x64
    float* Vs    = Ks + 64 * 64;       // [k][vd]  64x64
    float* Ps    = Vs + 64 * 64;       // [k][q]   64x64
    float* row_m = Ps + 64 * 64;       // [64]
    float* row_l = row_m + 64;         // [64]
    float* row_f = row_l + 64;         // [64]

    const int tid = threadIdx.x;
    const int tx = tid & 15;
    const int ty = tid >> 4;
    const int h  = blockIdx.y;
    const int b  = blockIdx.z;
    const size_t qbase = ((size_t)b * SS + blockIdx.x * 64) * DM + h * DK;

    // load Q tile transposed into Qs[d][q]
    {
        const int r  = tid >> 2;              // query row 0..63
        const int c0 = (tid & 3) * 16;        // d chunk
        const float* src = Q + qbase + (size_t)r * DM + c0;
        #pragma unroll
        for (int u = 0; u < 4; u++) {
            float4 a = *(const float4*)(src + u * 4);
            int d = c0 + u * 4;
            Qs[(d + 0) * 64 + r] = a.x;
            Qs[(d + 1) * 64 + r] = a.y;
            Qs[(d + 2) * 64 + r] = a.z;
            Qs[(d + 3) * 64 + r] = a.w;
        }
    }
    if (tid < 64) { row_m[tid] = -INFINITY; row_l[tid] = 0.0f; }

    float acc[4][4] = {};
    const float scale = 0.125f;   // 1/sqrt(64)

    for (int kt = 0; kt < SS / 64; kt++) {
        __syncthreads();   // protect Ks/Vs/Ps reuse + Q/stat init on first iter

        // load K tile (transposed) and V tile (direct)
        {
            const size_t kbase = ((size_t)b * SS + kt * 64) * DM + h * DK;
            const int r  = tid >> 2;
            const int c0 = (tid & 3) * 16;
            const float* ksrc = K + kbase + (size_t)r * DM + c0;
            const float* vsrc = V + kbase + (size_t)r * DM + c0;
            #pragma unroll
            for (int u = 0; u < 4; u++) {
                float4 a = *(const float4*)(ksrc + u * 4);
                int d = c0 + u * 4;
                Ks[(d + 0) * 64 + r] = a.x;
                Ks[(d + 1) * 64 + r] = a.y;
                Ks[(d + 2) * 64 + r] = a.z;
                Ks[(d + 3) * 64 + r] = a.w;
                *(float4*)&Vs[r * 64 + c0 + u * 4] = *(const float4*)(vsrc + u * 4);
            }
        }
        __syncthreads();

        // S = Q K^T (scaled)
        float s[4][4] = {};
        #pragma unroll 4
        for (int d = 0; d < 64; d++) {
            float4 a = *(float4*)&Qs[d * 64 + ty * 4];
            float4 bb = *(float4*)&Ks[d * 64 + tx * 4];
            float av[4] = {a.x, a.y, a.z, a.w};
            float bv[4] = {bb.x, bb.y, bb.z, bb.w};
            #pragma unroll
            for (int i = 0; i < 4; i++)
                #pragma unroll
                for (int j = 0; j < 4; j++)
                    s[i][j] = fmaf(av[i], bv[j], s[i][j]);
        }
        // store transposed: Ps[k][q]
        #pragma unroll
        for (int j = 0; j < 4; j++) {
            float4 w = make_float4(s[0][j] * scale, s[1][j] * scale,
                                   s[2][j] * scale, s[3][j] * scale);
            *(float4*)&Ps[(tx * 4 + j) * 64 + ty * 4] = w;
        }
        __syncthreads();

        // online softmax (one thread per query row)
        if (tid < 64) {
            const int q = tid;
            float m_old = row_m[q];
            float m = m_old;
            #pragma unroll 8
            for (int k2 = 0; k2 < 64; k2++)
                m = fmaxf(m, Ps[k2 * 64 + q]);
            float f = __expf(m_old - m);
            float sum = 0.0f;
            #pragma unroll 8
            for (int k2 = 0; k2 < 64; k2++) {
                float p = __expf(Ps[k2 * 64 + q] - m);
                Ps[k2 * 64 + q] = p;
                sum += p;
            }
            row_l[q] = row_l[q] * f + sum;
            row_m[q] = m;
            row_f[q] = f;
        }
        __syncthreads();

        // rescale accumulators, then O += P^T... O[q][vd] += sum_k P[k][q]*V[k][vd]
        #pragma unroll
        for (int i = 0; i < 4; i++) {
            float f = row_f[ty * 4 + i];
            #pragma unroll
            for (int j = 0; j < 4; j++) acc[i][j] *= f;
        }
        #pragma unroll 4
        for (int k2 = 0; k2 < 64; k2++) {
            float4 p = *(float4*)&Ps[k2 * 64 + ty * 4];
            float4 vv = *(float4*)&Vs[k2 * 64 + tx * 4];
            float pv[4] = {p.x, p.y, p.z, p.w};
            float vvv[4] = {vv.x, vv.y, vv.z, vv.w};
            #pragma unroll
            for (int i = 0; i < 4; i++)
                #pragma unroll
                for (int j = 0; j < 4; j++)
                    acc[i][j] = fmaf(pv[i], vvv[j], acc[i][j]);
        }
    }
    __syncthreads();

    // normalize and write context (head-concatenated layout)
    #pragma unroll
    for (int i = 0; i < 4; i++) {
        float invl = 1.0f / row_l[ty * 4 + i];
        float4 o = make_float4(acc[i][0] * invl, acc[i][1] * invl,
                               acc[i][2] * invl, acc[i][3] * invl);
        *(float4*)&O[qbase + (size_t)(ty * 4 + i) * DM + tx * 4] = o;
    }
}

// ---------------------------------------------------------------------------
extern "C" void kernel_launch(void* const* d_in, const int* in_sizes, int n_in,
                              void* d_out, int out_size) {
    const float* q  = (const float*)d_in[0];
    const float* k  = (const float*)d_in[1];
    const float* v  = (const float*)d_in[2];
    const float* Wq = (const float*)d_in[3];
    const float* Wk = (const float*)d_in[4];
    const float* Wv = (const float*)d_in[5];
    const float* Wo = (const float*)d_in[6];
    float* out = (float*)d_out;

    float *gQ, *gK, *gV, *gC;
    cudaGetSymbolAddress((void**)&gQ, g_Q);
    cudaGetSymbolAddress((void**)&gK, g_K);
    cudaGetSymbolAddress((void**)&gV, g_V);
    cudaGetSymbolAddress((void**)&gC, g_C);

    dim3 gThr(256);
    dim3 gGrid(DM / 64, MTOT / 64);

    // projections
    sgemm64<<<gGrid, gThr>>>(q, Wq, gQ, MTOT, DM, DM);
    sgemm64<<<gGrid, gThr>>>(k, Wk, gK, MTOT, DM, DM);
    sgemm64<<<gGrid, gThr>>>(v, Wv, gV, MTOT, DM, DM);

    // RoPE on Q, K
    const int total_pairs = MTOT * (DM / 2);
    rope_kernel<<<(total_pairs + 255) / 256, 256>>>(gQ, total_pairs);
    rope_kernel<<<(total_pairs + 255) / 256, 256>>>(gK, total_pairs);

    // flash attention
    const int smem = (4 * 64 * 64 + 3 * 64) * (int)sizeof(float);
    cudaFuncSetAttribute(flash_attn, cudaFuncAttributeMaxDynamicSharedMemorySize, smem);
    dim3 aGrid(SS / 64, NH, BB);
    flash_attn<<<aGrid, 256, smem>>>(gQ, gK, gV, gC);

    // output projection
    sgemm64<<<gGrid, gThr>>>(gC, Wo, out, MTOT, DM, DM);
}

// round 2
// speedup vs baseline: 2.7573x; 2.7573x over previous
#include <cuda_runtime.h>
#include <math.h>

#define BB 4
#define SS 2048
#define DM 1024
#define NH 16
#define DK 64
#define MTOT (BB*SS)

// scratch (device globals; allocation-free at launch time)
__device__ float g_Q[(size_t)MTOT*DM];
__device__ float g_K[(size_t)MTOT*DM];
__device__ float g_V[(size_t)MTOT*DM];
__device__ float g_C[(size_t)MTOT*DM];

// ---------------------------------------------------------------------------
// helpers
// ---------------------------------------------------------------------------
__device__ __forceinline__ float f2tf32f(float x) {
    unsigned y;
    asm("cvt.rna.tf32.f32 %0, %1;" : "=r"(y) : "f"(x));
    return __uint_as_float(y);
}

__device__ __forceinline__ void mma_tf32(float c[4],
                                         unsigned a0, unsigned a1, unsigned a2, unsigned a3,
                                         unsigned b0, unsigned b1) {
    asm volatile(
        "mma.sync.aligned.m16n8k8.row.col.f32.tf32.tf32.f32 "
        "{%0,%1,%2,%3},{%4,%5,%6,%7},{%8,%9},{%0,%1,%2,%3};"
        : "+f"(c[0]), "+f"(c[1]), "+f"(c[2]), "+f"(c[3])
        : "r"(a0), "r"(a1), "r"(a2), "r"(a3), "r"(b0), "r"(b1));
}

// ---------------------------------------------------------------------------
// TF32 GEMM: C[M,N] = A[M,K] * W[K,N], row-major, M=8192, N=K=1024.
// BM=128, BN=128, BK=16. 256 threads = 8 warps (4 m-rows x 2 n-cols),
// warp tile 32x64 via m16n8k8 (2 m-tiles x 8 n-tiles).
// ---------------------------------------------------------------------------
__global__ __launch_bounds__(256) void gemm_tf32(const float* __restrict__ A,
                                                 const float* __restrict__ W,
                                                 float* __restrict__ C) {
    __shared__ float As[128][20];   // [m][k], pad to 20 (stride%32==20 -> conflict-free frags)
    __shared__ float Bs[16][136];   // [k][n], pad to 136 (stride%32==8)

    const int tid  = threadIdx.x;
    const int wid  = tid >> 5;
    const int lane = tid & 31;
    const int g    = lane >> 2;      // group id 0..7
    const int tig  = lane & 3;       // thread in group
    const int rw   = wid >> 1;       // warp m index 0..3
    const int cw   = wid & 1;        // warp n index 0..1
    const int m0   = blockIdx.y * 128;
    const int n0   = blockIdx.x * 128;

    float acc[2][8][4];
    #pragma unroll
    for (int i = 0; i < 2; i++)
        #pragma unroll
        for (int j = 0; j < 8; j++)
            #pragma unroll
            for (int l = 0; l < 4; l++) acc[i][j][l] = 0.0f;

    const int lr = tid >> 1;          // A tile row 0..127
    const int lc = (tid & 1) * 8;     // A tile col base
    const int wr = tid >> 4;          // B tile row 0..15
    const int wc = (tid & 15) * 8;    // B tile col base

    for (int k0 = 0; k0 < DM; k0 += 16) {
        __syncthreads();
        // load + convert A tile (128x16)
        {
            const float* src = A + (size_t)(m0 + lr) * DM + k0 + lc;
            float4 v0 = *(const float4*)src;
            float4 v1 = *(const float4*)(src + 4);
            float4 t0 = make_float4(f2tf32f(v0.x), f2tf32f(v0.y), f2tf32f(v0.z), f2tf32f(v0.w));
            float4 t1 = make_float4(f2tf32f(v1.x), f2tf32f(v1.y), f2tf32f(v1.z), f2tf32f(v1.w));
            *(float4*)&As[lr][lc]     = t0;
            *(float4*)&As[lr][lc + 4] = t1;
        }
        // load + convert B tile (16x128)
        {
            const float* src = W + (size_t)(k0 + wr) * DM + n0 + wc;
            float4 v0 = *(const float4*)src;
            float4 v1 = *(const float4*)(src + 4);
            float4 t0 = make_float4(f2tf32f(v0.x), f2tf32f(v0.y), f2tf32f(v0.z), f2tf32f(v0.w));
            float4 t1 = make_float4(f2tf32f(v1.x), f2tf32f(v1.y), f2tf32f(v1.z), f2tf32f(v1.w));
            *(float4*)&Bs[wr][wc]     = t0;
            *(float4*)&Bs[wr][wc + 4] = t1;
        }
        __syncthreads();

        #pragma unroll
        for (int ks = 0; ks < 16; ks += 8) {
            unsigned a[2][4];
            #pragma unroll
            for (int mt = 0; mt < 2; mt++) {
                const int r = rw * 32 + mt * 16;
                a[mt][0] = __float_as_uint(As[r + g][ks + tig]);
                a[mt][1] = __float_as_uint(As[r + g + 8][ks + tig]);
                a[mt][2] = __float_as_uint(As[r + g][ks + tig + 4]);
                a[mt][3] = __float_as_uint(As[r + g + 8][ks + tig + 4]);
            }
            unsigned b[8][2];
            #pragma unroll
            for (int nt = 0; nt < 8; nt++) {
                const int n = cw * 64 + nt * 8;
                b[nt][0] = __float_as_uint(Bs[ks + tig][n + g]);
                b[nt][1] = __float_as_uint(Bs[ks + tig + 4][n + g]);
            }
            #pragma unroll
            for (int mt = 0; mt < 2; mt++)
                #pragma unroll
                for (int nt = 0; nt < 8; nt++)
                    mma_tf32(acc[mt][nt], a[mt][0], a[mt][1], a[mt][2], a[mt][3],
                             b[nt][0], b[nt][1]);
        }
    }

    // epilogue
    #pragma unroll
    for (int mt = 0; mt < 2; mt++) {
        const int r = m0 + rw * 32 + mt * 16 + g;
        #pragma unroll
        for (int nt = 0; nt < 8; nt++) {
            const int c = n0 + cw * 64 + nt * 8 + 2 * tig;
            *(float2*)&C[(size_t)r * DM + c]       = make_float2(acc[mt][nt][0], acc[mt][nt][1]);
            *(float2*)&C[(size_t)(r + 8) * DM + c] = make_float2(acc[mt][nt][2], acc[mt][nt][3]);
        }
    }
}

// ---------------------------------------------------------------------------
// RoPE (fp32; matches the fp32 reference math closely enough)
// ---------------------------------------------------------------------------
__global__ void rope_kernel(float* __restrict__ X, int total_pairs) {
    int idx = blockIdx.x * blockDim.x + threadIdx.x;
    if (idx >= total_pairs) return;
    const int p   = idx & 511;          // pair within row
    const int m   = idx >> 9;           // row
    const int pos = m & (SS - 1);
    const int i   = p & 31;             // pair within head

    // inv_freq = 10000^(-i/32) = 2^(-i*log2(10000)/32)
    const float inv = exp2f(-(float)i * 0.41524101186f);
    const float ang = (float)pos * inv;
    float s, c;
    sincosf(ang, &s, &c);

    float* base = X + (size_t)m * DM + p * 2;
    float x1 = base[0];
    float x2 = base[1];
    base[0] = x1 * c - x2 * s;
    base[1] = x1 * s + x2 * c;
}

// ---------------------------------------------------------------------------
// Flash attention, tf32 tensor cores. BM=BN=DK=64. 128 threads = 4 warps,
// each warp owns 16 query rows; softmax stats fully in registers.
// ---------------------------------------------------------------------------
__global__ __launch_bounds__(128) void flash_tf32(const float* __restrict__ Q,
                                                  const float* __restrict__ K,
                                                  const float* __restrict__ V,
                                                  float* __restrict__ O) {
    extern __shared__ float sm[];
    float* Qs = sm;                 // [64][68]
    float* Ks = Qs + 64 * 68;       // [64][68]
    float* Vs = Ks + 64 * 68;       // [64][72]
    float* Ps = Vs + 64 * 72;       // [64][68]

    const int tid  = threadIdx.x;
    const int wid  = tid >> 5;
    const int lane = tid & 31;
    const int g    = lane >> 2;
    const int tig  = lane & 3;
    const int h    = blockIdx.y;
    const int b    = blockIdx.z;
    const int q0   = wid * 16;
    const size_t qbase = ((size_t)b * SS + blockIdx.x * 64) * DM + h * DK;

    // load Q tile (64x64), convert to tf32
    {
        const int r  = tid >> 1;
        const int c0 = (tid & 1) * 32;
        const float* src = Q + qbase + (size_t)r * DM + c0;
        #pragma unroll
        for (int u = 0; u < 8; u++) {
            float4 v = *(const float4*)(src + u * 4);
            float4 t = make_float4(f2tf32f(v.x), f2tf32f(v.y), f2tf32f(v.z), f2tf32f(v.w));
            *(float4*)&Qs[r * 68 + c0 + u * 4] = t;
        }
    }

    float o[8][4];
    #pragma unroll
    for (int nt = 0; nt < 8; nt++)
        #pragma unroll
        for (int j = 0; j < 4; j++) o[nt][j] = 0.0f;
    float mrow0 = -INFINITY, mrow1 = -INFINITY;
    float lrow0 = 0.0f, lrow1 = 0.0f;
    const float scale = 0.125f;

    for (int kt = 0; kt < SS / 64; kt++) {
        __syncthreads();
        // load K,V tiles (64x64 each), convert to tf32
        {
            const size_t kb = ((size_t)b * SS + kt * 64) * DM + h * DK;
            const int r  = tid >> 1;
            const int c0 = (tid & 1) * 32;
            const float* ksrc = K + kb + (size_t)r * DM + c0;
            const float* vsrc = V + kb + (size_t)r * DM + c0;
            #pragma unroll
            for (int u = 0; u < 8; u++) {
                float4 v = *(const float4*)(ksrc + u * 4);
                float4 t = make_float4(f2tf32f(v.x), f2tf32f(v.y), f2tf32f(v.z), f2tf32f(v.w));
                *(float4*)&Ks[r * 68 + c0 + u * 4] = t;
                float4 w = *(const float4*)(vsrc + u * 4);
                float4 tw = make_float4(f2tf32f(w.x), f2tf32f(w.y), f2tf32f(w.z), f2tf32f(w.w));
                *(float4*)&Vs[r * 72 + c0 + u * 4] = tw;
            }
        }
        __syncthreads();

        // S = Q K^T (64x64 per CTA; this warp: rows q0..q0+15, all 64 cols)
        float s[8][4];
        #pragma unroll
        for (int nt = 0; nt < 8; nt++)
            #pragma unroll
            for (int j = 0; j < 4; j++) s[nt][j] = 0.0f;

        #pragma unroll
        for (int k8 = 0; k8 < 8; k8++) {
            const int kk = k8 * 8;
            unsigned a0 = __float_as_uint(Qs[(q0 + g) * 68 + kk + tig]);
            unsigned a1 = __float_as_uint(Qs[(q0 + g + 8) * 68 + kk + tig]);
            unsigned a2 = __float_as_uint(Qs[(q0 + g) * 68 + kk + tig + 4]);
            unsigned a3 = __float_as_uint(Qs[(q0 + g + 8) * 68 + kk + tig + 4]);
            #pragma unroll
            for (int nt = 0; nt < 8; nt++) {
                unsigned b0 = __float_as_uint(Ks[(nt * 8 + g) * 68 + kk + tig]);
                unsigned b1 = __float_as_uint(Ks[(nt * 8 + g) * 68 + kk + tig + 4]);
                mma_tf32(s[nt], a0, a1, a2, a3, b0, b1);
            }
        }

        // scale
        #pragma unroll
        for (int nt = 0; nt < 8; nt++)
            #pragma unroll
            for (int j = 0; j < 4; j++) s[nt][j] *= scale;

        // online softmax (rows g and g+8 of this warp's 16 rows)
        float mx0 = -INFINITY, mx1 = -INFINITY;
        #pragma unroll
        for (int nt = 0; nt < 8; nt++) {
            mx0 = fmaxf(mx0, fmaxf(s[nt][0], s[nt][1]));
            mx1 = fmaxf(mx1, fmaxf(s[nt][2], s[nt][3]));
        }
        mx0 = fmaxf(mx0, __shfl_xor_sync(0xffffffffu, mx0, 1));
        mx0 = fmaxf(mx0, __shfl_xor_sync(0xffffffffu, mx0, 2));
        mx1 = fmaxf(mx1, __shfl_xor_sync(0xffffffffu, mx1, 1));
        mx1 = fmaxf(mx1, __shfl_xor_sync(0xffffffffu, mx1, 2));

        const float mn0 = fmaxf(mrow0, mx0);
        const float mn1 = fmaxf(mrow1, mx1);
        const float f0 = __expf(mrow0 - mn0);
        const float f1 = __expf(mrow1 - mn1);
        mrow0 = mn0; mrow1 = mn1;

        float sum0 = 0.0f, sum1 = 0.0f;
        #pragma unroll
        for (int nt = 0; nt < 8; nt++) {
            float p0 = __expf(s[nt][0] - mn0);
            float p1 = __expf(s[nt][1] - mn0);
            float p2 = __expf(s[nt][2] - mn1);
            float p3 = __expf(s[nt][3] - mn1);
            sum0 += p0 + p1;
            sum1 += p2 + p3;
            const int kc = nt * 8 + 2 * tig;
            *(float2*)&Ps[(q0 + g) * 68 + kc]     = make_float2(f2tf32f(p0), f2tf32f(p1));
            *(float2*)&Ps[(q0 + g + 8) * 68 + kc] = make_float2(f2tf32f(p2), f2tf32f(p3));
        }
        sum0 += __shfl_xor_sync(0xffffffffu, sum0, 1);
        sum0 += __shfl_xor_sync(0xffffffffu, sum0, 2);
        sum1 += __shfl_xor_sync(0xffffffffu, sum1, 1);
        sum1 += __shfl_xor_sync(0xffffffffu, sum1, 2);
        lrow0 = lrow0 * f0 + sum0;
        lrow1 = lrow1 * f1 + sum1;

        // rescale O accumulators
        #pragma unroll
        for (int nt = 0; nt < 8; nt++) {
            o[nt][0] *= f0; o[nt][1] *= f0;
            o[nt][2] *= f1; o[nt][3] *= f1;
        }

        __syncwarp();

        // O += P V   (P: warp's own 16 rows x 64 keys; V: 64 keys x 64 d)
        #pragma unroll
        for (int k8 = 0; k8 < 8; k8++) {
            const int kk = k8 * 8;
            unsigned a0 = __float_as_uint(Ps[(q0 + g) * 68 + kk + tig]);
            unsigned a1 = __float_as_uint(Ps[(q0 + g + 8) * 68 + kk + tig]);
            unsigned a2 = __float_as_uint(Ps[(q0 + g) * 68 + kk + tig + 4]);
            unsigned a3 = __float_as_uint(Ps[(q0 + g + 8) * 68 + kk + tig + 4]);
            #pragma unroll
            for (int nt = 0; nt < 8; nt++) {
                unsigned b0 = __float_as_uint(Vs[(kk + tig) * 72 + nt * 8 + g]);
                unsigned b1 = __float_as_uint(Vs[(kk + tig + 4) * 72 + nt * 8 + g]);
                mma_tf32(o[nt], a0, a1, a2, a3, b0, b1);
            }
        }
        __syncwarp();
    }

    // normalize + write context (head-concatenated layout)
    const float inv0 = 1.0f / lrow0;
    const float inv1 = 1.0f / lrow1;
    #pragma unroll
    for (int nt = 0; nt < 8; nt++) {
        const int c = nt * 8 + 2 * tig;
        *(float2*)&O[qbase + (size_t)(q0 + g) * DM + c] =
            make_float2(o[nt][0] * inv0, o[nt][1] * inv0);
        *(float2*)&O[qbase + (size_t)(q0 + g + 8) * DM + c] =
            make_float2(o[nt][2] * inv1, o[nt][3] * inv1);
    }
}

// ---------------------------------------------------------------------------
extern "C" void kernel_launch(void* const* d_in, const int* in_sizes, int n_in,
                              void* d_out, int out_size) {
    const float* q  = (const float*)d_in[0];
    const float* k  = (const float*)d_in[1];
    const float* v  = (const float*)d_in[2];
    const float* Wq = (const float*)d_in[3];
    const float* Wk = (const float*)d_in[4];
    const float* Wv = (const float*)d_in[5];
    const float* Wo = (const float*)d_in[6];
    float* out = (float*)d_out;

    float *gQ, *gK, *gV, *gC;
    cudaGetSymbolAddress((void**)&gQ, g_Q);
    cudaGetSymbolAddress((void**)&gK, g_K);
    cudaGetSymbolAddress((void**)&gV, g_V);
    cudaGetSymbolAddress((void**)&gC, g_C);

    dim3 gGrid(DM / 128, MTOT / 128);

    // projections (tf32 tensor cores)
    gemm_tf32<<<gGrid, 256>>>(q, Wq, gQ);
    gemm_tf32<<<gGrid, 256>>>(k, Wk, gK);
    gemm_tf32<<<gGrid, 256>>>(v, Wv, gV);

    // RoPE on Q, K (fp32)
    const int total_pairs = MTOT * (DM / 2);
    rope_kernel<<<(total_pairs + 255) / 256, 256>>>(gQ, total_pairs);
    rope_kernel<<<(total_pairs + 255) / 256, 256>>>(gK, total_pairs);

    // flash attention (tf32 tensor cores)
    const int smem = (64 * 68 * 3 + 64 * 72) * (int)sizeof(float);
    cudaFuncSetAttribute(flash_tf32, cudaFuncAttributeMaxDynamicSharedMemorySize, smem);
    dim3 aGrid(SS / 64, NH, BB);
    flash_tf32<<<aGrid, 128, smem>>>(gQ, gK, gV, gC);

    // output projection
    gemm_tf32<<<gGrid, 256>>>(gC, Wo, out);
}

// round 3
// speedup vs baseline: 3.8422x; 1.3935x over previous
#include <cuda_runtime.h>
#include <math.h>

#define BB 4
#define SS 2048
#define DM 1024
#define NH 16
#define DK 64
#define MTOT (BB*SS)

// scratch (device globals; allocation-free at launch time)
__device__ float g_Q[(size_t)MTOT*DM];
__device__ float g_K[(size_t)MTOT*DM];
__device__ float g_V[(size_t)MTOT*DM];
__device__ float g_C[(size_t)MTOT*DM];

// ---------------------------------------------------------------------------
// helpers
// ---------------------------------------------------------------------------
__device__ __forceinline__ unsigned f2tf32u(float x) {
    unsigned y;
    asm("cvt.rna.tf32.f32 %0, %1;" : "=r"(y) : "f"(x));
    return y;
}
__device__ __forceinline__ float f2tf32f(float x) { return __uint_as_float(f2tf32u(x)); }

__device__ __forceinline__ void mma_tf32(float c[4],
                                         unsigned a0, unsigned a1, unsigned a2, unsigned a3,
                                         unsigned b0, unsigned b1) {
    asm volatile(
        "mma.sync.aligned.m16n8k8.row.col.f32.tf32.tf32.f32 "
        "{%0,%1,%2,%3},{%4,%5,%6,%7},{%8,%9},{%0,%1,%2,%3};"
        : "+f"(c[0]), "+f"(c[1]), "+f"(c[2]), "+f"(c[3])
        : "r"(a0), "r"(a1), "r"(a2), "r"(a3), "r"(b0), "r"(b1));
}

__device__ __forceinline__ void cp16(void* dst_smem, const void* src_gmem) {
    unsigned s = (unsigned)__cvta_generic_to_shared(dst_smem);
    asm volatile("cp.async.cg.shared.global [%0], [%1], 16;" :: "r"(s), "l"(src_gmem));
}
__device__ __forceinline__ void cp_commit() { asm volatile("cp.async.commit_group;"); }
template<int N> __device__ __forceinline__ void cp_wait() {
    asm volatile("cp.async.wait_group %0;" :: "n"(N));
}

// log2(10000)/32
#define ROPE_L2 0.41524101186f

// ---------------------------------------------------------------------------
// TF32 GEMM: C[M,N] = A[M,K] * W[K,N]. BM=BN=128, BK=16, 256 thr = 8 warps
// (4x2), warp tile 32x64. cp.async double-buffered. Optional fused RoPE.
// ---------------------------------------------------------------------------
template<bool ROPE>
__global__ __launch_bounds__(256) void gemm_tf32_v2(const float* __restrict__ A,
                                                    const float* __restrict__ W,
                                                    float* __restrict__ C) {
    __shared__ float As[2][128][20];   // raw fp32, [m][k] padded
    __shared__ float Bs[2][16][136];   // raw fp32, [k][n] padded

    const int tid  = threadIdx.x;
    const int wid  = tid >> 5;
    const int lane = tid & 31;
    const int g    = lane >> 2;
    const int tig  = lane & 3;
    const int rw   = wid >> 1;
    const int cw   = wid & 1;
    const int m0   = blockIdx.y * 128;
    const int n0   = blockIdx.x * 128;

    const int lr = tid >> 1;          // A row 0..127
    const int lc = (tid & 1) * 8;     // A col base {0,8}
    const int wr = tid >> 4;          // B row 0..15
    const int wc = (tid & 15) * 8;    // B col base

    float acc[2][8][4];
    #pragma unroll
    for (int i = 0; i < 2; i++)
        #pragma unroll
        for (int j = 0; j < 8; j++)
            #pragma unroll
            for (int l = 0; l < 4; l++) acc[i][j][l] = 0.0f;

    const float* asrc = A + (size_t)(m0 + lr) * DM + lc;
    const float* bsrc = W + (size_t)wr * DM + n0 + wc;

    // prefetch tile 0
    cp16(&As[0][lr][lc],     asrc);
    cp16(&As[0][lr][lc + 4], asrc + 4);
    cp16(&Bs[0][wr][wc],     bsrc);
    cp16(&Bs[0][wr][wc + 4], bsrc + 4);
    cp_commit();

    const int NT = DM / 16;
    for (int t = 0; t < NT; t++) {
        const int buf = t & 1;
        if (t + 1 < NT) {
            const float* a2 = asrc + (t + 1) * 16;
            const float* b2 = bsrc + (size_t)(t + 1) * 16 * DM;
            cp16(&As[buf ^ 1][lr][lc],     a2);
            cp16(&As[buf ^ 1][lr][lc + 4], a2 + 4);
            cp16(&Bs[buf ^ 1][wr][wc],     b2);
            cp16(&Bs[buf ^ 1][wr][wc + 4], b2 + 4);
            cp_commit();
            cp_wait<1>();
        } else {
            cp_wait<0>();
        }
        __syncthreads();

        #pragma unroll
        for (int ks = 0; ks < 16; ks += 8) {
            unsigned a[2][4];
            #pragma unroll
            for (int mt = 0; mt < 2; mt++) {
                const int r = rw * 32 + mt * 16;
                a[mt][0] = f2tf32u(As[buf][r + g][ks + tig]);
                a[mt][1] = f2tf32u(As[buf][r + g + 8][ks + tig]);
                a[mt][2] = f2tf32u(As[buf][r + g][ks + tig + 4]);
                a[mt][3] = f2tf32u(As[buf][r + g + 8][ks + tig + 4]);
            }
            unsigned b[8][2];
            #pragma unroll
            for (int nt = 0; nt < 8; nt++) {
                const int n = cw * 64 + nt * 8;
                b[nt][0] = f2tf32u(Bs[buf][ks + tig][n + g]);
                b[nt][1] = f2tf32u(Bs[buf][ks + tig + 4][n + g]);
            }
            #pragma unroll
            for (int mt = 0; mt < 2; mt++)
                #pragma unroll
                for (int nt = 0; nt < 8; nt++)
                    mma_tf32(acc[mt][nt], a[mt][0], a[mt][1], a[mt][2], a[mt][3],
                             b[nt][0], b[nt][1]);
        }
        __syncthreads();
    }

    // epilogue (optionally fused RoPE: each (pair of) acc values is one rope pair)
    #pragma unroll
    for (int mt = 0; mt < 2; mt++) {
        const int r = m0 + rw * 32 + mt * 16 + g;
        const int pos0 = r & (SS - 1);
        const int pos8 = (r + 8) & (SS - 1);
        #pragma unroll
        for (int nt = 0; nt < 8; nt++) {
            const int c = n0 + cw * 64 + nt * 8 + 2 * tig;
            float y0 = acc[mt][nt][0], y1 = acc[mt][nt][1];
            float y2 = acc[mt][nt][2], y3 = acc[mt][nt][3];
            if (ROPE) {
                const int i = (c & 63) >> 1;
                const float inv = exp2f(-(float)i * ROPE_L2);
                float s0, c0, s8, c8;
                sincosf((float)pos0 * inv, &s0, &c0);
                sincosf((float)pos8 * inv, &s8, &c8);
                float x1 = y0, x2 = y1;
                y0 = x1 * c0 - x2 * s0;
                y1 = x1 * s0 + x2 * c0;
                x1 = y2; x2 = y3;
                y2 = x1 * c8 - x2 * s8;
                y3 = x1 * s8 + x2 * c8;
            }
            *(float2*)&C[(size_t)r * DM + c]       = make_float2(y0, y1);
            *(float2*)&C[(size_t)(r + 8) * DM + c] = make_float2(y2, y3);
        }
    }
}

// ---------------------------------------------------------------------------
// Flash attention, tf32. BM=128 q rows, BN=64 keys/iter, DK=64.
// 256 threads = 8 warps, each warp owns 16 q rows; Q fragments in registers;
// K/V cp.async double-buffered (raw fp32, cvt at fragment load).
// ---------------------------------------------------------------------------
__global__ __launch_bounds__(256, 2) void flash_tf32_v2(const float* __restrict__ Q,
                                                        const float* __restrict__ K,
                                                        const float* __restrict__ V,
                                                        float* __restrict__ O) {
    extern __shared__ float sm[];
    float* Ks = sm;                    // [2][64][68]
    float* Vs = Ks + 2 * 64 * 68;      // [2][64][72]
    float* Ps = Vs + 2 * 64 * 72;      // [128][68]

    const int tid  = threadIdx.x;
    const int wid  = tid >> 5;
    const int lane = tid & 31;
    const int g    = lane >> 2;
    const int tig  = lane & 3;
    const int h    = blockIdx.y;
    const int b    = blockIdx.z;
    const int q0   = wid * 16;
    const size_t qbase = ((size_t)b * SS + blockIdx.x * 128) * DM + h * DK;
    const size_t kvbase = (size_t)b * SS * DM + h * DK;

    // Q fragments straight from gmem (scaled by 1/sqrt(dk), tf32-rounded)
    unsigned qf[8][4];
    {
        const float* q_r0 = Q + qbase + (size_t)(q0 + g) * DM;
        const float* q_r8 = Q + qbase + (size_t)(q0 + g + 8) * DM;
        #pragma unroll
        for (int k8 = 0; k8 < 8; k8++) {
            const int cc = k8 * 8 + tig;
            qf[k8][0] = f2tf32u(0.125f * __ldg(q_r0 + cc));
            qf[k8][1] = f2tf32u(0.125f * __ldg(q_r8 + cc));
            qf[k8][2] = f2tf32u(0.125f * __ldg(q_r0 + cc + 4));
            qf[k8][3] = f2tf32u(0.125f * __ldg(q_r8 + cc + 4));
        }
    }

    // KV prefetch helpers
    const int pr = tid >> 2;            // row 0..63
    const int pc = (tid & 3) * 16;      // col base
    auto kv_prefetch = [&](int kt, int buf) {
        const float* ksrc = K + kvbase + ((size_t)kt * 64 + pr) * DM + pc;
        const float* vsrc = V + kvbase + ((size_t)kt * 64 + pr) * DM + pc;
        float* kd = Ks + buf * 64 * 68 + pr * 68 + pc;
        float* vd = Vs + buf * 64 * 72 + pr * 72 + pc;
        #pragma unroll
        for (int j = 0; j < 4; j++) {
            cp16(kd + j * 4, ksrc + j * 4);
            cp16(vd + j * 4, vsrc + j * 4);
        }
        cp_commit();
    };

    kv_prefetch(0, 0);

    float o[8][4];
    #pragma unroll
    for (int nt = 0; nt < 8; nt++)
        #pragma unroll
        for (int j = 0; j < 4; j++) o[nt][j] = 0.0f;
    float mrow0 = -INFINITY, mrow1 = -INFINITY;
    float lrow0 = 0.0f, lrow1 = 0.0f;

    const int NKT = SS / 64;
    for (int kt = 0; kt < NKT; kt++) {
        const int buf = kt & 1;
        __syncthreads();   // all warps done reading buf^1 (iter kt-1) before overwrite
        if (kt + 1 < NKT) {
            kv_prefetch(kt + 1, buf ^ 1);
            cp_wait<1>();
        } else {
            cp_wait<0>();
        }
        __syncthreads();

        const float* KsB = Ks + buf * 64 * 68;
        const float* VsB = Vs + buf * 64 * 72;

        // S = (Q*scale) K^T  -- this warp: 16 rows x 64 cols
        float s[8][4];
        #pragma unroll
        for (int nt = 0; nt < 8; nt++)
            #pragma unroll
            for (int j = 0; j < 4; j++) s[nt][j] = 0.0f;

        #pragma unroll
        for (int k8 = 0; k8 < 8; k8++) {
            const int kk = k8 * 8;
            #pragma unroll
            for (int nt = 0; nt < 8; nt++) {
                unsigned b0 = f2tf32u(KsB[(nt * 8 + g) * 68 + kk + tig]);
                unsigned b1 = f2tf32u(KsB[(nt * 8 + g) * 68 + kk + tig + 4]);
                mma_tf32(s[nt], qf[k8][0], qf[k8][1], qf[k8][2], qf[k8][3], b0, b1);
            }
        }

        // online softmax (rows q0+g and q0+g+8)
        float mx0 = -INFINITY, mx1 = -INFINITY;
        #pragma unroll
        for (int nt = 0; nt < 8; nt++) {
            mx0 = fmaxf(mx0, fmaxf(s[nt][0], s[nt][1]));
            mx1 = fmaxf(mx1, fmaxf(s[nt][2], s[nt][3]));
        }
        mx0 = fmaxf(mx0, __shfl_xor_sync(0xffffffffu, mx0, 1));
        mx0 = fmaxf(mx0, __shfl_xor_sync(0xffffffffu, mx0, 2));
        mx1 = fmaxf(mx1, __shfl_xor_sync(0xffffffffu, mx1, 1));
        mx1 = fmaxf(mx1, __shfl_xor_sync(0xffffffffu, mx1, 2));

        const float mn0 = fmaxf(mrow0, mx0);
        const float mn1 = fmaxf(mrow1, mx1);
        const float f0 = __expf(mrow0 - mn0);
        const float f1 = __expf(mrow1 - mn1);
        mrow0 = mn0; mrow1 = mn1;

        float sum0 = 0.0f, sum1 = 0.0f;
        #pragma unroll
        for (int nt = 0; nt < 8; nt++) {
            float p0 = __expf(s[nt][0] - mn0);
            float p1 = __expf(s[nt][1] - mn0);
            float p2 = __expf(s[nt][2] - mn1);
            float p3 = __expf(s[nt][3] - mn1);
            sum0 += p0 + p1;
            sum1 += p2 + p3;
            const int kc = nt * 8 + 2 * tig;
            *(float2*)&Ps[(q0 + g) * 68 + kc]     = make_float2(f2tf32f(p0), f2tf32f(p1));
            *(float2*)&Ps[(q0 + g + 8) * 68 + kc] = make_float2(f2tf32f(p2), f2tf32f(p3));
        }
        sum0 += __shfl_xor_sync(0xffffffffu, sum0, 1);
        sum0 += __shfl_xor_sync(0xffffffffu, sum0, 2);
        sum1 += __shfl_xor_sync(0xffffffffu, sum1, 1);
        sum1 += __shfl_xor_sync(0xffffffffu, sum1, 2);
        lrow0 = lrow0 * f0 + sum0;
        lrow1 = lrow1 * f1 + sum1;

        #pragma unroll
        for (int nt = 0; nt < 8; nt++) {
            o[nt][0] *= f0; o[nt][1] *= f0;
            o[nt][2] *= f1; o[nt][3] *= f1;
        }

        __syncwarp();   // Ps store -> Ps load (same warp's rows only)

        // O += P V
        #pragma unroll
        for (int k8 = 0; k8 < 8; k8++) {
            const int kk = k8 * 8;
            unsigned a0 = __float_as_uint(Ps[(q0 + g) * 68 + kk + tig]);
            unsigned a1 = __float_as_uint(Ps[(q0 + g + 8) * 68 + kk + tig]);
            unsigned a2 = __float_as_uint(Ps[(q0 + g) * 68 + kk + tig + 4]);
            unsigned a3 = __float_as_uint(Ps[(q0 + g + 8) * 68 + kk + tig + 4]);
            #pragma unroll
            for (int nt = 0; nt < 8; nt++) {
                unsigned b0 = f2tf32u(VsB[(kk + tig) * 72 + nt * 8 + g]);
                unsigned b1 = f2tf32u(VsB[(kk + tig + 4) * 72 + nt * 8 + g]);
                mma_tf32(o[nt], a0, a1, a2, a3, b0, b1);
            }
        }
    }

    // normalize + write context
    const float inv0 = 1.0f / lrow0;
    const float inv1 = 1.0f / lrow1;
    #pragma unroll
    for (int nt = 0; nt < 8; nt++) {
        const int c = nt * 8 + 2 * tig;
        *(float2*)&O[qbase + (size_t)(q0 + g) * DM + c] =
            make_float2(o[nt][0] * inv0, o[nt][1] * inv0);
        *(float2*)&O[qbase + (size_t)(q0 + g + 8) * DM + c] =
            make_float2(o[nt][2] * inv1, o[nt][3] * inv1);
    }
}

// ---------------------------------------------------------------------------
extern "C" void kernel_launch(void* const* d_in, const int* in_sizes, int n_in,
                              void* d_out, int out_size) {
    const float* q  = (const float*)d_in[0];
    const float* k  = (const float*)d_in[1];
    const float* v  = (const float*)d_in[2];
    const float* Wq = (const float*)d_in[3];
    const float* Wk = (const float*)d_in[4];
    const float* Wv = (const float*)d_in[5];
    const float* Wo = (const float*)d_in[6];
    float* out = (float*)d_out;

    float *gQ, *gK, *gV, *gC;
    cudaGetSymbolAddress((void**)&gQ, g_Q);
    cudaGetSymbolAddress((void**)&gK, g_K);
    cudaGetSymbolAddress((void**)&gV, g_V);
    cudaGetSymbolAddress((void**)&gC, g_C);

    dim3 gGrid(DM / 128, MTOT / 128);

    // projections + fused RoPE on Q,K
    gemm_tf32_v2<true ><<<gGrid, 256>>>(q, Wq, gQ);
    gemm_tf32_v2<true ><<<gGrid, 256>>>(k, Wk, gK);
    gemm_tf32_v2<false><<<gGrid, 256>>>(v, Wv, gV);

    // flash attention
    const int smem = (2 * 64 * 68 + 2 * 64 * 72 + 128 * 68) * (int)sizeof(float);
    cudaFuncSetAttribute(flash_tf32_v2, cudaFuncAttributeMaxDynamicSharedMemorySize, smem);
    dim3 aGrid(SS / 128, NH, BB);
    flash_tf32_v2<<<aGrid, 256, smem>>>(gQ, gK, gV, gC);

    // output projection
    gemm_tf32_v2<false><<<gGrid, 256>>>(gC, Wo, out);
}